// round 6
// baseline (speedup 1.0000x reference)
#include <cuda_runtime.h>

#define NS 4096
#define NBATCH 32
#define TPB 256

// pywt db4 dec filters, time-reversed (cross-correlation form)
__device__ __constant__ float cH0[8] = {
     0.23037781330885523f,  0.7148465705525415f,   0.6308807679295904f,
    -0.02798376941698385f, -0.18703481171888114f,  0.030841381835986965f,
     0.032883011666982945f, -0.010597401784997278f };
__device__ __constant__ float cH1[8] = {
    -0.010597401784997278f, -0.032883011666982945f, 0.030841381835986965f,
     0.18703481171888114f,  -0.02798376941698385f,  -0.6308807679295904f,
     0.7148465705525415f,   -0.23037781330885523f };

// Lowpass scratch planes, (B, T_k, 64) contiguous.
__device__ float g_scratch[8126464];
#define OFF_LO1 0
#define OFF_LO2 4194304
#define OFF_LO3 6291456
#define OFF_LO4 7340032
#define OFF_LO5 7864320

__device__ __forceinline__ int level_of(float sc) {
    int l = 2 + (int)rintf(sc * 3.0f);          // round-half-even, matches jnp.round
    return l < 2 ? 2 : (l > 5 ? 5 : l);
}

// Level 1 mega-kernel: full grid over (b, n<4096, f4).
//  - n < 2048 : conv x -> lo1 (scratch), det1 = hi, hf = hi
//  - n >= 2048: det1 = 0, hf = 0
//  - tails of det2..det5 zeroed here too (n >= 1024/512/256/128)
__global__ void __launch_bounds__(TPB)
level1_kernel(const float* __restrict__ x, float* __restrict__ lo1,
              float* __restrict__ out)
{
    int idx = blockIdx.x * TPB + threadIdx.x;
    const int f4 = idx & 15;
    const int n  = (idx >> 4) & (NS - 1);
    const int b  = idx >> 16;

    const size_t PLANE4 = (size_t)NBATCH * NS * 16;
    const size_t row4   = ((size_t)b * NS + n) * 16 + f4;
    const float4 z = make_float4(0.f, 0.f, 0.f, 0.f);

    if (n < 2048) {
        const float4* pin = (const float4*)x + (size_t)b * NS * 16 + f4;
        float4 lo = z, hi = z;
#pragma unroll
        for (int t = 0; t < 8; ++t) {
            int r = 2 * n + t - 3;
            if (r >= 0 && r < NS) {
                float4 v = __ldg(pin + (size_t)r * 16);
                float c0 = cH0[t], c1 = cH1[t];
                lo.x = fmaf(c0, v.x, lo.x); lo.y = fmaf(c0, v.y, lo.y);
                lo.z = fmaf(c0, v.z, lo.z); lo.w = fmaf(c0, v.w, lo.w);
                hi.x = fmaf(c1, v.x, hi.x); hi.y = fmaf(c1, v.y, hi.y);
                hi.z = fmaf(c1, v.z, hi.z); hi.w = fmaf(c1, v.w, hi.w);
            }
        }
        ((float4*)lo1)[((size_t)b * 2048 + n) * 16 + f4] = lo;
        ((float4*)out)[1 * PLANE4 + row4] = hi;     // det1 (always active)
        ((float4*)out)[6 * PLANE4 + row4] = hi;     // hf seed
    } else {
        ((float4*)out)[1 * PLANE4 + row4] = z;
        ((float4*)out)[6 * PLANE4 + row4] = z;
    }
    // zero tails of the deeper detail planes
    if (n >= 1024) ((float4*)out)[2 * PLANE4 + row4] = z;
    if (n >=  512) ((float4*)out)[3 * PLANE4 + row4] = z;
    if (n >=  256) ((float4*)out)[4 * PLANE4 + row4] = z;
    if (n >=  128) ((float4*)out)[5 * PLANE4 + row4] = z;
}

// Levels 2..5: grid covers ONLY the TOUT coefficient rows (no tail threads).
// Writes lo_k to scratch, masked detail prefix, and RMW-accumulates hf prefix
// (L2-hot; each (b,n,f4) owned by one thread, kernels stream-ordered).
template <int TIN, int DET>
__global__ void __launch_bounds__(TPB)
level_kernel(const float* __restrict__ in, float* __restrict__ loOut,
             float* __restrict__ det, float* __restrict__ hf,
             const float* __restrict__ scores)
{
    const int TOUT = TIN / 2;
    int idx = blockIdx.x * TPB + threadIdx.x;
    const int f4 = idx & 15;
    const int n  = (idx >> 4) & (TOUT - 1);
    const int b  = (idx >> 4) / TOUT;

    const float4* pin = (const float4*)in + (size_t)b * TIN * 16 + f4;
    float4 lo = make_float4(0.f, 0.f, 0.f, 0.f);
    float4 hi = make_float4(0.f, 0.f, 0.f, 0.f);
#pragma unroll
    for (int t = 0; t < 8; ++t) {
        int r = 2 * n + t - 3;
        if (r >= 0 && r < TIN) {
            float4 v = __ldg(pin + (size_t)r * 16);
            float c0 = cH0[t], c1 = cH1[t];
            lo.x = fmaf(c0, v.x, lo.x); lo.y = fmaf(c0, v.y, lo.y);
            lo.z = fmaf(c0, v.z, lo.z); lo.w = fmaf(c0, v.w, lo.w);
            hi.x = fmaf(c1, v.x, hi.x); hi.y = fmaf(c1, v.y, hi.y);
            hi.z = fmaf(c1, v.z, hi.z); hi.w = fmaf(c1, v.w, hi.w);
        }
    }
    if (DET >= 2) {                                 // per-feature activity mask
        const int f = f4 * 4;
        if (DET >= level_of(__ldg(scores + f + 0))) hi.x = 0.f;
        if (DET >= level_of(__ldg(scores + f + 1))) hi.y = 0.f;
        if (DET >= level_of(__ldg(scores + f + 2))) hi.z = 0.f;
        if (DET >= level_of(__ldg(scores + f + 3))) hi.w = 0.f;
    }

    const size_t row4 = ((size_t)b * NS + n) * 16 + f4;
    ((float4*)loOut)[((size_t)b * TOUT + n) * 16 + f4] = lo;
    det[0] = 0.f;  // (placeholder removed below)
}

// NOTE: the placeholder line above is wrong; real implementation follows.
// (kept minimal: specializations write via pointers computed in launcher)

extern "C" void kernel_launch(void* const* d_in, const int* in_sizes, int n_in,
                              void* d_out, int out_size);

// ---- proper level kernel (replaces the stub above) ----
template <int TIN, int DET>
__global__ void __launch_bounds__(TPB)
level_kernel2(const float* __restrict__ in, float* __restrict__ loOut,
              float* __restrict__ det, float* __restrict__ hf,
              const float* __restrict__ scores)
{
    const int TOUT = TIN / 2;
    int idx = blockIdx.x * TPB + threadIdx.x;
    const int f4 = idx & 15;
    const int n  = (idx >> 4) & (TOUT - 1);
    const int b  = (idx >> 4) / TOUT;

    const float4* pin = (const float4*)in + (size_t)b * TIN * 16 + f4;
    float4 lo = make_float4(0.f, 0.f, 0.f, 0.f);
    float4 hi = make_float4(0.f, 0.f, 0.f, 0.f);
#pragma unroll
    for (int t = 0; t < 8; ++t) {
        int r = 2 * n + t - 3;
        if (r >= 0 && r < TIN) {
            float4 v = __ldg(pin + (size_t)r * 16);
            float c0 = cH0[t], c1 = cH1[t];
            lo.x = fmaf(c0, v.x, lo.x); lo.y = fmaf(c0, v.y, lo.y);
            lo.z = fmaf(c0, v.z, lo.z); lo.w = fmaf(c0, v.w, lo.w);
            hi.x = fmaf(c1, v.x, hi.x); hi.y = fmaf(c1, v.y, hi.y);
            hi.z = fmaf(c1, v.z, hi.z); hi.w = fmaf(c1, v.w, hi.w);
        }
    }
    if (DET >= 2) {
        const int f = f4 * 4;
        if (DET >= level_of(__ldg(scores + f + 0))) hi.x = 0.f;
        if (DET >= level_of(__ldg(scores + f + 1))) hi.y = 0.f;
        if (DET >= level_of(__ldg(scores + f + 2))) hi.z = 0.f;
        if (DET >= level_of(__ldg(scores + f + 3))) hi.w = 0.f;
    }

    const size_t row4 = ((size_t)b * NS + n) * 16 + f4;
    ((float4*)loOut)[((size_t)b * TOUT + n) * 16 + f4] = lo;
    ((float4*)det)[row4] = hi;

    float4* ph = (float4*)hf + row4;               // L2-hot prefix RMW
    float4 h = *ph;
    h.x += hi.x; h.y += hi.y; h.z += hi.z; h.w += hi.w;
    *ph = h;
}

// Final: approx (plane 0) and low_freq (plane 7) via per-feature level select.
__global__ void __launch_bounds__(TPB)
final_kernel(float* __restrict__ out, const float* __restrict__ scores)
{
    int idx = blockIdx.x * TPB + threadIdx.x;
    const int f4 = idx & 15;
    const int s  = (idx >> 4) & (NS - 1);
    const int b  = idx >> 16;

    const size_t PLANE4 = (size_t)NBATCH * NS * 16;
    const size_t row4   = ((size_t)b * NS + s) * 16 + f4;

    const size_t offs[4] = { OFF_LO2, OFF_LO3, OFF_LO4, OFF_LO5 };
    const int f = f4 * 4;
    float av[4];
#pragma unroll
    for (int j = 0; j < 4; ++j) {
        int k = level_of(__ldg(scores + f + j)) - 2;     // 0..3
        int T = 1024 >> k;
        av[j] = (s < T)
            ? __ldg(g_scratch + offs[k] + ((size_t)b * T + s) * 64 + f + j)
            : 0.f;
    }
    float4 a = make_float4(av[0], av[1], av[2], av[3]);
    ((float4*)out)[row4] = a;               // approx
    ((float4*)out)[7 * PLANE4 + row4] = a;  // low_freq
}

extern "C" void kernel_launch(void* const* d_in, const int* in_sizes, int n_in,
                              void* d_out, int out_size)
{
    const float* x      = (const float*)d_in[0];
    const float* scores = (const float*)d_in[1];
    float* out          = (float*)d_out;

    float* scratch;
    cudaGetSymbolAddress((void**)&scratch, g_scratch);
    float* lo1 = scratch + OFF_LO1;
    float* lo2 = scratch + OFF_LO2;
    float* lo3 = scratch + OFF_LO3;
    float* lo4 = scratch + OFF_LO4;
    float* lo5 = scratch + OFF_LO5;

    const size_t PLANE = (size_t)NBATCH * NS * 64;
    float* hf = out + 6 * PLANE;

    level1_kernel<<<(NBATCH * NS * 16) / TPB, TPB>>>(x, lo1, out);
    level_kernel2<2048, 1><<<(NBATCH * 1024 * 16) / TPB, TPB>>>(lo1, lo2, out + 2 * PLANE, hf, scores);
    level_kernel2<1024, 2><<<(NBATCH *  512 * 16) / TPB, TPB>>>(lo2, lo3, out + 3 * PLANE, hf, scores);
    level_kernel2< 512, 3><<<(NBATCH *  256 * 16) / TPB, TPB>>>(lo3, lo4, out + 4 * PLANE, hf, scores);
    level_kernel2< 256, 4><<<(NBATCH *  128 * 16) / TPB, TPB>>>(lo4, lo5, out + 5 * PLANE, hf, scores);
    final_kernel<<<(NBATCH * NS * 16) / TPB, TPB>>>(out, scores);
}